// round 9
// baseline (speedup 1.0000x reference)
#include <cuda_runtime.h>
#include <cuda_bf16.h>
#include <cstdint>

#define NC   4096
#define NS   16384
#define CCH  256
#define CS   128
#define DIN  384
#define HID  256

// Packed split-bf16 activation/weight buffers: row m = [hi(K) | lo(K)] bf16.
__device__ __align__(16) unsigned short g_ycat[(size_t)NS * (2 * DIN)];
__device__ __align__(16) unsigned short g_h[(size_t)NS * (2 * HID)];
__device__ __align__(16) unsigned short g_w1[(size_t)HID * (2 * DIN)];
__device__ __align__(16) unsigned short g_w2[(size_t)HID * (2 * HID)];

// ---------------------------------------------------------------------------
// helpers
// ---------------------------------------------------------------------------
__device__ __forceinline__ uint32_t smem_u32(const void* p) {
    uint32_t a;
    asm("{ .reg .u64 t; cvta.to.shared.u64 t, %1; cvt.u32.u64 %0, t; }" : "=r"(a) : "l"(p));
    return a;
}
__device__ __forceinline__ void cp16(uint32_t dst, const void* src) {
    asm volatile("cp.async.cg.shared.global [%0], [%1], 16;" :: "r"(dst), "l"(src));
}
__device__ __forceinline__ void cp_commit() { asm volatile("cp.async.commit_group;"); }
template<int N> __device__ __forceinline__ void cp_wait() {
    asm volatile("cp.async.wait_group %0;" :: "n"(N));
}
__device__ __forceinline__ void ldm4(uint32_t* r, uint32_t a) {
    asm volatile("ldmatrix.sync.aligned.m8n8.x4.shared.b16 {%0,%1,%2,%3}, [%4];"
                 : "=r"(r[0]), "=r"(r[1]), "=r"(r[2]), "=r"(r[3]) : "r"(a));
}
__device__ __forceinline__ void mma16816(float* c, const uint32_t* a, const uint32_t* b) {
    asm volatile("mma.sync.aligned.m16n8k16.row.col.f32.bf16.bf16.f32 "
                 "{%0,%1,%2,%3},{%4,%5,%6,%7},{%8,%9},{%0,%1,%2,%3};"
                 : "+f"(c[0]), "+f"(c[1]), "+f"(c[2]), "+f"(c[3])
                 : "r"(a[0]), "r"(a[1]), "r"(a[2]), "r"(a[3]), "r"(b[0]), "r"(b[1]));
}
__device__ __forceinline__ unsigned short f2bf(float v) {
    return __bfloat16_as_ushort(__float2bfloat16_rn(v));
}
__device__ __forceinline__ float bf2f(unsigned short u) {
    return __bfloat162float(__ushort_as_bfloat16(u));
}
__device__ __forceinline__ uint32_t pack_bf2(float a, float b) {
    __nv_bfloat162 h = __float22bfloat162_rn(make_float2(a, b));
    return *(uint32_t*)&h;
}
__device__ __forceinline__ void split_store4(unsigned short* hi, unsigned short* lo, float4 o) {
    uint32_t ha = pack_bf2(o.x, o.y);
    uint32_t hb = pack_bf2(o.z, o.w);
    float f0 = __uint_as_float(ha << 16), f1 = __uint_as_float(ha & 0xFFFF0000u);
    float f2 = __uint_as_float(hb << 16), f3 = __uint_as_float(hb & 0xFFFF0000u);
    uint32_t la = pack_bf2(o.x - f0, o.y - f1);
    uint32_t lb = pack_bf2(o.z - f2, o.w - f3);
    *(uint2*)hi = make_uint2(ha, hb);
    *(uint2*)lo = make_uint2(la, lb);
}

// ---------------------------------------------------------------------------
// Kernel 1: KNN — 16 threads/point (1024 blocks x 256 thr, 16 pts/block),
// segment-resident smem, shared boundary table, dot-form rank scan.
// ---------------------------------------------------------------------------
#define SEG_CAP  1664                 // float4 slots (26KB)
#define KNN_SMEM (SEG_CAP * 16)
#define NBATCH   4
#define PPB      16                   // points per block
#define TPP      16                   // threads per point

__global__ __launch_bounds__(256, 8)
void knn_interp_kernel(const float* __restrict__ x,
                       const float* __restrict__ pos,
                       const int*   __restrict__ batch,
                       const float* __restrict__ x_skip,
                       const float* __restrict__ pos_skip,
                       const int*   __restrict__ batch_skip,
                       const float* __restrict__ W1,
                       const float* __restrict__ W2,
                       float* __restrict__ out, int out_size)
{
    extern __shared__ float4 pos4[];           // [SEG_CAP]
    __shared__ int   sIdx[PPB][3];
    __shared__ float sW[PPB][3];
    __shared__ int   sSegB[NBATCH + 1];

    const int tid = threadIdx.x;
    const int p_local = tid >> 4;              // 0..15
    const int q       = tid & 15;              // scan part 0..15
    const int gp      = blockIdx.x * PPB + p_local;
    const int gid     = blockIdx.x * 256 + tid;

    // ---- batch boundary table ----
    if (tid <= NBATCH) {
        int b = tid;
        int v;
        if (b == 0) v = 0;
        else if (b == NBATCH) v = NC;
        else {
            int lo = 0, hi = NC;
            while (lo < hi) { int m = (lo + hi) >> 1; if (batch[m] < b) lo = m + 1; else hi = m; }
            v = lo;
        }
        sSegB[b] = v;
    }

    // ---- weight prep: coalesced reads, scattered transposed writes ----
    for (int i = gid; i < DIN * HID; i += 1024 * 256) {
        int k = i >> 8, n = i & 255;
        float v = W1[i];
        unsigned short hh = f2bf(v);
        g_w1[(size_t)n * (2 * DIN) + k]       = hh;
        g_w1[(size_t)n * (2 * DIN) + DIN + k] = f2bf(v - bf2f(hh));
    }
    for (int i = gid; i < HID * HID; i += 1024 * 256) {
        int k = i >> 8, n = i & 255;
        float v = W2[i];
        unsigned short hh = f2bf(v);
        g_w2[(size_t)n * (2 * HID) + k]       = hh;
        g_w2[(size_t)n * (2 * HID) + HID + k] = f2bf(v - bf2f(hh));
    }

    __syncthreads();

    // ---- block segment union + own bounds ----
    const int mbLo = batch_skip[blockIdx.x * PPB];
    const int mbHi = batch_skip[blockIdx.x * PPB + PPB - 1];
    const int seg_lo  = sSegB[mbLo];
    const int fill_hi = min(sSegB[mbHi + 1], seg_lo + SEG_CAP);

    const float px = pos_skip[3 * gp + 0];
    const float py = pos_skip[3 * gp + 1];
    const float pz = pos_skip[3 * gp + 2];
    const int   mb = batch_skip[gp];
    const int   segs = sSegB[mb];
    const int   sege = sSegB[mb + 1];

    // ---- fill smem with union segment ----
    for (int j = seg_lo + tid; j < fill_hi; j += 256) {
        float cx = pos[3 * j + 0], cy = pos[3 * j + 1], cz = pos[3 * j + 2];
        pos4[j - seg_lo] = make_float4(cx, cy, cz, fmaf(cx, cx, fmaf(cy, cy, cz * cz)));
    }
    __syncthreads();

    // ---- phase 1: 1/16-segment scan on d' = |c|^2 - 2 p.c ----
    const float nx = -2.0f * px, ny = -2.0f * py, nz = -2.0f * pz;
    float d0 = 3e38f, d1 = 3e38f, d2 = 3e38f;
    int   i0 = segs,  i1 = segs,  i2 = segs;

    auto ins = [&](float dn, int jn) {
        bool b2 = dn < d2;
        float td = b2 ? dn : d2; int ti = b2 ? jn : i2;
        bool b1 = td < d1;
        d2 = b1 ? d1 : td; i2 = b1 ? i1 : ti;
        float ud = b1 ? td : d1; int ui = b1 ? ti : i1;
        bool b0 = ud < d0;
        d1 = b0 ? d0 : ud; i1 = b0 ? i0 : ui;
        d0 = b0 ? ud : d0; i0 = b0 ? ui : i0;
    };

    const int scan_hi = min(sege, fill_hi);
    int j = segs + q;
    #pragma unroll 4
    for (; j < scan_hi; j += TPP) {
        float4 c = pos4[j - seg_lo];
        float s = fmaf(nx, c.x, fmaf(ny, c.y, fmaf(nz, c.z, c.w)));
        if (s < d2) ins(s, j);      // rare
    }
    // overflow safety (boundary blocks only): continue from global
    for (; j < sege; j += TPP) {
        float cx = pos[3 * j + 0], cy = pos[3 * j + 1], cz = pos[3 * j + 2];
        float cw = fmaf(cx, cx, fmaf(cy, cy, cz * cz));
        float s = fmaf(nx, cx, fmaf(ny, cy, fmaf(nz, cz, cw)));
        if (s < d2) ins(s, j);
    }

    // ---- merge across the 16 lanes of this point ----
    #pragma unroll
    for (int m = 1; m <= 8; m <<= 1) {
        float e0 = __shfl_xor_sync(0xFFFFFFFFu, d0, m);
        float e1 = __shfl_xor_sync(0xFFFFFFFFu, d1, m);
        float e2 = __shfl_xor_sync(0xFFFFFFFFu, d2, m);
        int   f0 = __shfl_xor_sync(0xFFFFFFFFu, i0, m);
        int   f1 = __shfl_xor_sync(0xFFFFFFFFu, i1, m);
        int   f2 = __shfl_xor_sync(0xFFFFFFFFu, i2, m);
        ins(e0, f0); ins(e1, f1); ins(e2, f2);
    }

    if (q == 0) {
        // exact squared distances for the 3 winners (smem when resident)
        auto fetch = [&](int idx) -> float3 {
            if (idx >= seg_lo && idx < fill_hi) {
                float4 c = pos4[idx - seg_lo];
                return make_float3(c.x, c.y, c.z);
            }
            return make_float3(pos[3 * idx + 0], pos[3 * idx + 1], pos[3 * idx + 2]);
        };
        float3 c0 = fetch(i0), c1 = fetch(i1), c2 = fetch(i2);
        float ax = c0.x - px, ay = c0.y - py, az = c0.z - pz;
        float bx = c1.x - px, by = c1.y - py, bz = c1.z - pz;
        float cx = c2.x - px, cy = c2.y - py, cz = c2.z - pz;
        float e0 = fmaf(ax, ax, fmaf(ay, ay, az * az));
        float e1 = fmaf(bx, bx, fmaf(by, by, bz * bz));
        float e2 = fmaf(cx, cx, fmaf(cy, cy, cz * cz));
        float w0 = 1.0f / fmaxf(e0, 1e-16f);
        float w1v = 1.0f / fmaxf(e1, 1e-16f);
        float w2v = 1.0f / fmaxf(e2, 1e-16f);
        float inv_sw = 1.0f / (w0 + w1v + w2v);
        sIdx[p_local][0] = i0; sIdx[p_local][1] = i1; sIdx[p_local][2] = i2;
        sW[p_local][0] = w0 * inv_sw; sW[p_local][1] = w1v * inv_sw; sW[p_local][2] = w2v * inv_sw;

        if (out_size > NS * HID) {
            out[NS * HID + 3 * gp + 0] = px;
            out[NS * HID + 3 * gp + 1] = py;
            out[NS * HID + 3 * gp + 2] = pz;
            out[NS * HID + NS * 3 + gp] = (float)mb;
        }
    }
    __syncthreads();

    // ---- phase 2: warp-cooperative gather + packed bf16 split store ----
    const int warp = tid >> 5;
    const int lane = tid & 31;

    for (int r = warp; r < PPB; r += 8) {
        const int g  = blockIdx.x * PPB + r;
        const int j0 = sIdx[r][0], j1 = sIdx[r][1], j2 = sIdx[r][2];
        const float a = sW[r][0], b = sW[r][1], c = sW[r][2];

        const float4* X0 = (const float4*)(x + (size_t)j0 * CCH);
        const float4* X1 = (const float4*)(x + (size_t)j1 * CCH);
        const float4* X2 = (const float4*)(x + (size_t)j2 * CCH);
        unsigned short* Y = g_ycat + (size_t)g * (2 * DIN);

        #pragma unroll
        for (int v = lane; v < CCH / 4; v += 32) {
            float4 A = X0[v], B = X1[v], Cv = X2[v];
            float4 o;
            o.x = fmaf(a, A.x, fmaf(b, B.x, c * Cv.x));
            o.y = fmaf(a, A.y, fmaf(b, B.y, c * Cv.y));
            o.z = fmaf(a, A.z, fmaf(b, B.z, c * Cv.z));
            o.w = fmaf(a, A.w, fmaf(b, B.w, c * Cv.w));
            split_store4(Y + v * 4, Y + DIN + v * 4, o);
        }
        float4 sv = ((const float4*)(x_skip + (size_t)g * CS))[lane];
        split_store4(Y + CCH + lane * 4, Y + DIN + CCH + lane * 4, sv);
    }
}

// ---------------------------------------------------------------------------
// bf16x3 mma.sync GEMM: C[M,256] = relu(A @ B^T + bias)
// CTA tile 128x128, BK=32, 256 threads (8 warps = 4m x 2n), 3-stage cp.async.
// ---------------------------------------------------------------------------
#define GSTAGES 3
#define GEMM_SMEM (GSTAGES * 32768)

template<int K, bool PACK>
__global__ __launch_bounds__(256, 1)
void mma_gemm(const unsigned short* __restrict__ Apk,
              const unsigned short* __restrict__ Bpk,
              const float* __restrict__ bias,
              void* __restrict__ Cout)
{
    constexpr int NCHK = K / 32;
    extern __shared__ uint8_t smem[];
    const uint32_t sb = smem_u32(smem);

    const int tid   = threadIdx.x;
    const int lane  = tid & 31;
    const int wid   = tid >> 5;
    const int warpM = wid & 3;
    const int warpN = wid >> 2;
    const int m0    = blockIdx.x * 128;
    const int n0    = blockIdx.y * 128;

    const uint8_t* Abytes = (const uint8_t*)Apk + (size_t)m0 * (4 * K);
    const uint8_t* Bbytes = (const uint8_t*)Bpk + (size_t)n0 * (4 * K);

    auto issue = [&](int kc, int st) {
        uint32_t sA = sb + st * 32768, sB = sA + 16384;
        #pragma unroll
        for (int i = 0; i < 4; ++i) {
            int id  = tid + 256 * i;
            int row = id >> 3, g = id & 7;
            int off = row * (4 * K) + (g < 4 ? kc * 64 + g * 16
                                             : 2 * K + kc * 64 + (g - 4) * 16);
            uint32_t d = (uint32_t)(row * 128) + (uint32_t)((g ^ (row & 7)) << 4);
            cp16(sA + d, Abytes + off);
            cp16(sB + d, Bbytes + off);
        }
        cp_commit();
    };

    issue(0, 0);
    issue(1, 1);

    float acc[2][8][4] = {};

    for (int c = 0; c < NCHK; ++c) {
        if (c <= NCHK - 2) cp_wait<1>(); else cp_wait<0>();
        __syncthreads();

        const int st = c % GSTAGES;
        const uint32_t sA = sb + st * 32768, sB = sA + 16384;

        #pragma unroll
        for (int kk = 0; kk < 2; ++kk) {
            uint32_t ah[2][4], al[2][4];
            #pragma unroll
            for (int mf = 0; mf < 2; ++mf) {
                const int rm  = warpM * 32 + mf * 16 + (lane & 15);
                const int sub = lane >> 4;
                const uint32_t base = sA + rm * 128;
                ldm4(ah[mf], base + (((kk * 2 + sub) ^ (rm & 7)) << 4));
                ldm4(al[mf], base + (((4 + kk * 2 + sub) ^ (rm & 7)) << 4));
            }
            uint32_t bh[8][2], bl[8][2];
            #pragma unroll
            for (int nq = 0; nq < 4; ++nq) {
                const int rn  = warpN * 64 + nq * 16 + (lane & 7) + ((lane >> 4) << 3);
                const int sub = (lane >> 3) & 1;
                const uint32_t base = sB + rn * 128;
                uint32_t t[4];
                ldm4(t, base + (((kk * 2 + sub) ^ (rn & 7)) << 4));
                bh[2 * nq][0] = t[0]; bh[2 * nq][1] = t[1];
                bh[2 * nq + 1][0] = t[2]; bh[2 * nq + 1][1] = t[3];
                ldm4(t, base + (((4 + kk * 2 + sub) ^ (rn & 7)) << 4));
                bl[2 * nq][0] = t[0]; bl[2 * nq][1] = t[1];
                bl[2 * nq + 1][0] = t[2]; bl[2 * nq + 1][1] = t[3];
            }
            #pragma unroll
            for (int mf = 0; mf < 2; ++mf)
                #pragma unroll
                for (int nf = 0; nf < 8; ++nf) {
                    mma16816(acc[mf][nf], ah[mf], bh[nf]);
                    mma16816(acc[mf][nf], ah[mf], bl[nf]);
                    mma16816(acc[mf][nf], al[mf], bh[nf]);
                }
        }

        if (c + GSTAGES - 1 < NCHK) issue(c + GSTAGES - 1, (c + GSTAGES - 1) % GSTAGES);
    }

    #pragma unroll
    for (int mf = 0; mf < 2; ++mf) {
        const int mrow = m0 + warpM * 32 + mf * 16 + (lane >> 2);
        #pragma unroll
        for (int nf = 0; nf < 8; ++nf) {
            const int n = n0 + warpN * 64 + nf * 8 + 2 * (lane & 3);
            const float b0v = __ldg(bias + n), b1v = __ldg(bias + n + 1);
            float v00 = fmaxf(acc[mf][nf][0] + b0v, 0.0f);
            float v01 = fmaxf(acc[mf][nf][1] + b1v, 0.0f);
            float v10 = fmaxf(acc[mf][nf][2] + b0v, 0.0f);
            float v11 = fmaxf(acc[mf][nf][3] + b1v, 0.0f);
            if (PACK) {
                unsigned short* H = (unsigned short*)Cout;
                uint32_t hi0 = pack_bf2(v00, v01);
                float g0 = __uint_as_float(hi0 << 16), g1 = __uint_as_float(hi0 & 0xFFFF0000u);
                uint32_t lo0 = pack_bf2(v00 - g0, v01 - g1);
                uint32_t hi1 = pack_bf2(v10, v11);
                float g2 = __uint_as_float(hi1 << 16), g3 = __uint_as_float(hi1 & 0xFFFF0000u);
                uint32_t lo1 = pack_bf2(v10 - g2, v11 - g3);
                *(uint32_t*)(H + (size_t)mrow * (2 * HID) + n)             = hi0;
                *(uint32_t*)(H + (size_t)mrow * (2 * HID) + HID + n)       = lo0;
                *(uint32_t*)(H + (size_t)(mrow + 8) * (2 * HID) + n)       = hi1;
                *(uint32_t*)(H + (size_t)(mrow + 8) * (2 * HID) + HID + n) = lo1;
            } else {
                float* O = (float*)Cout;
                float2 p0 = {v00, v01}, p1 = {v10, v11};
                *(float2*)(O + (size_t)mrow * 256 + n)       = p0;
                *(float2*)(O + (size_t)(mrow + 8) * 256 + n) = p1;
            }
        }
    }
}

// ---------------------------------------------------------------------------
extern "C" void kernel_launch(void* const* d_in, const int* in_sizes, int n_in,
                              void* d_out, int out_size)
{
    const float* x          = (const float*)d_in[0];
    const float* pos        = (const float*)d_in[1];
    const int*   batch      = (const int*)  d_in[2];
    const float* x_skip     = (const float*)d_in[3];
    const float* pos_skip   = (const float*)d_in[4];
    const int*   batch_skip = (const int*)  d_in[5];
    const float* W1         = (const float*)d_in[6];
    const float* b1         = (const float*)d_in[7];
    const float* W2         = (const float*)d_in[8];
    const float* b2         = (const float*)d_in[9];
    float* out = (float*)d_out;

    unsigned short *ycat, *h, *w1, *w2;
    cudaGetSymbolAddress((void**)&ycat, g_ycat);
    cudaGetSymbolAddress((void**)&h,    g_h);
    cudaGetSymbolAddress((void**)&w1,   g_w1);
    cudaGetSymbolAddress((void**)&w2,   g_w2);

    cudaFuncSetAttribute(knn_interp_kernel,    cudaFuncAttributeMaxDynamicSharedMemorySize, KNN_SMEM);
    cudaFuncSetAttribute(mma_gemm<DIN, true>,  cudaFuncAttributeMaxDynamicSharedMemorySize, GEMM_SMEM);
    cudaFuncSetAttribute(mma_gemm<HID, false>, cudaFuncAttributeMaxDynamicSharedMemorySize, GEMM_SMEM);

    // 1) KNN + interpolate + concat (+ weight prep + tail outputs)
    knn_interp_kernel<<<NS / PPB, 256, KNN_SMEM>>>(x, pos, batch, x_skip, pos_skip, batch_skip,
                                                   W1, W2, out, out_size);

    // 2) h = relu(ycat @ W1 + b1)  — packed bf16 output
    {
        dim3 grid(NS / 128, 2);
        mma_gemm<DIN, true><<<grid, 256, GEMM_SMEM>>>(ycat, w1, b1, h);
    }
    // 3) out = relu(h @ W2 + b2)   — fp32 output
    {
        dim3 grid(NS / 128, 2);
        mma_gemm<HID, false><<<grid, 256, GEMM_SMEM>>>(h, w2, b2, out);
    }
}

// round 10
// speedup vs baseline: 1.4413x; 1.4413x over previous
#include <cuda_runtime.h>
#include <cuda_bf16.h>
#include <cstdint>

#define NC   4096
#define NS   16384
#define CCH  256
#define CS   128
#define DIN  384
#define HID  256

// Packed split-bf16 activation/weight buffers: row m = [hi(K) | lo(K)] bf16.
__device__ __align__(16) unsigned short g_ycat[(size_t)NS * (2 * DIN)];
__device__ __align__(16) unsigned short g_h[(size_t)NS * (2 * HID)];
__device__ __align__(16) unsigned short g_w1[(size_t)HID * (2 * DIN)];
__device__ __align__(16) unsigned short g_w2[(size_t)HID * (2 * HID)];

// ---------------------------------------------------------------------------
// helpers
// ---------------------------------------------------------------------------
__device__ __forceinline__ uint32_t smem_u32(const void* p) {
    uint32_t a;
    asm("{ .reg .u64 t; cvta.to.shared.u64 t, %1; cvt.u32.u64 %0, t; }" : "=r"(a) : "l"(p));
    return a;
}
__device__ __forceinline__ void cp16(uint32_t dst, const void* src) {
    asm volatile("cp.async.cg.shared.global [%0], [%1], 16;" :: "r"(dst), "l"(src));
}
__device__ __forceinline__ void cp_commit() { asm volatile("cp.async.commit_group;"); }
template<int N> __device__ __forceinline__ void cp_wait() {
    asm volatile("cp.async.wait_group %0;" :: "n"(N));
}
__device__ __forceinline__ void ldm4(uint32_t* r, uint32_t a) {
    asm volatile("ldmatrix.sync.aligned.m8n8.x4.shared.b16 {%0,%1,%2,%3}, [%4];"
                 : "=r"(r[0]), "=r"(r[1]), "=r"(r[2]), "=r"(r[3]) : "r"(a));
}
__device__ __forceinline__ void mma16816(float* c, const uint32_t* a, const uint32_t* b) {
    asm volatile("mma.sync.aligned.m16n8k16.row.col.f32.bf16.bf16.f32 "
                 "{%0,%1,%2,%3},{%4,%5,%6,%7},{%8,%9},{%0,%1,%2,%3};"
                 : "+f"(c[0]), "+f"(c[1]), "+f"(c[2]), "+f"(c[3])
                 : "r"(a[0]), "r"(a[1]), "r"(a[2]), "r"(a[3]), "r"(b[0]), "r"(b[1]));
}
__device__ __forceinline__ unsigned short f2bf(float v) {
    return __bfloat16_as_ushort(__float2bfloat16_rn(v));
}
__device__ __forceinline__ float bf2f(unsigned short u) {
    return __bfloat162float(__ushort_as_bfloat16(u));
}
__device__ __forceinline__ uint32_t pack_bf2(float a, float b) {
    __nv_bfloat162 h = __float22bfloat162_rn(make_float2(a, b));
    return *(uint32_t*)&h;
}
__device__ __forceinline__ void split_store4(unsigned short* hi, unsigned short* lo, float4 o) {
    uint32_t ha = pack_bf2(o.x, o.y);
    uint32_t hb = pack_bf2(o.z, o.w);
    float f0 = __uint_as_float(ha << 16), f1 = __uint_as_float(ha & 0xFFFF0000u);
    float f2 = __uint_as_float(hb << 16), f3 = __uint_as_float(hb & 0xFFFF0000u);
    uint32_t la = pack_bf2(o.x - f0, o.y - f1);
    uint32_t lb = pack_bf2(o.z - f2, o.w - f3);
    *(uint2*)hi = make_uint2(ha, hb);
    *(uint2*)lo = make_uint2(la, lb);
}

// ---------------------------------------------------------------------------
// Kernel 1: KNN — PPB=32/TPP=8 (round-8 config), batched-min screening scan.
// ---------------------------------------------------------------------------
#define SEG_CAP  1664                 // float4 slots (26KB)
#define KNN_SMEM (SEG_CAP * 16)
#define NBATCH   4
#define PPB      32
#define TPP      8

__global__ __launch_bounds__(256, 8)
void knn_interp_kernel(const float* __restrict__ x,
                       const float* __restrict__ pos,
                       const int*   __restrict__ batch,
                       const float* __restrict__ x_skip,
                       const float* __restrict__ pos_skip,
                       const int*   __restrict__ batch_skip,
                       const float* __restrict__ W1,
                       const float* __restrict__ W2,
                       float* __restrict__ out, int out_size)
{
    extern __shared__ float4 pos4[];           // [SEG_CAP]
    __shared__ int   sIdx[PPB][3];
    __shared__ float sW[PPB][3];
    __shared__ int   sSegB[NBATCH + 1];

    const int tid = threadIdx.x;
    const int p_local = tid >> 3;              // 0..31
    const int q       = tid & 7;               // scan part 0..7
    const int gp      = blockIdx.x * PPB + p_local;
    const int gid     = blockIdx.x * 256 + tid;

    // ---- batch boundary table ----
    if (tid <= NBATCH) {
        int b = tid;
        int v;
        if (b == 0) v = 0;
        else if (b == NBATCH) v = NC;
        else {
            int lo = 0, hi = NC;
            while (lo < hi) { int m = (lo + hi) >> 1; if (batch[m] < b) lo = m + 1; else hi = m; }
            v = lo;
        }
        sSegB[b] = v;
    }

    // ---- weight prep: coalesced reads, scattered transposed writes ----
    for (int i = gid; i < DIN * HID; i += 512 * 256) {
        int k = i >> 8, n = i & 255;
        float v = W1[i];
        unsigned short hh = f2bf(v);
        g_w1[(size_t)n * (2 * DIN) + k]       = hh;
        g_w1[(size_t)n * (2 * DIN) + DIN + k] = f2bf(v - bf2f(hh));
    }
    for (int i = gid; i < HID * HID; i += 512 * 256) {
        int k = i >> 8, n = i & 255;
        float v = W2[i];
        unsigned short hh = f2bf(v);
        g_w2[(size_t)n * (2 * HID) + k]       = hh;
        g_w2[(size_t)n * (2 * HID) + HID + k] = f2bf(v - bf2f(hh));
    }

    __syncthreads();

    // ---- block segment union + own bounds ----
    const int mbLo = batch_skip[blockIdx.x * PPB];
    const int mbHi = batch_skip[blockIdx.x * PPB + PPB - 1];
    const int seg_lo  = sSegB[mbLo];
    const int fill_hi = min(sSegB[mbHi + 1], seg_lo + SEG_CAP);

    const float px = pos_skip[3 * gp + 0];
    const float py = pos_skip[3 * gp + 1];
    const float pz = pos_skip[3 * gp + 2];
    const int   mb = batch_skip[gp];
    const int   segs = sSegB[mb];
    const int   sege = sSegB[mb + 1];

    // ---- fill smem with union segment ----
    for (int j = seg_lo + tid; j < fill_hi; j += 256) {
        float cx = pos[3 * j + 0], cy = pos[3 * j + 1], cz = pos[3 * j + 2];
        pos4[j - seg_lo] = make_float4(cx, cy, cz, fmaf(cx, cx, fmaf(cy, cy, cz * cz)));
    }
    __syncthreads();

    // ---- phase 1: 1/8-segment scan on d' = |c|^2 - 2 p.c, batched min ----
    const float nx = -2.0f * px, ny = -2.0f * py, nz = -2.0f * pz;
    float d0 = 3e38f, d1 = 3e38f, d2 = 3e38f;
    int   i0 = segs,  i1 = segs,  i2 = segs;

    auto ins = [&](float dn, int jn) {
        bool b2 = dn < d2;
        float td = b2 ? dn : d2; int ti = b2 ? jn : i2;
        bool b1 = td < d1;
        d2 = b1 ? d1 : td; i2 = b1 ? i1 : ti;
        float ud = b1 ? td : d1; int ui = b1 ? ti : i1;
        bool b0 = ud < d0;
        d1 = b0 ? d0 : ud; i1 = b0 ? i0 : ui;
        d0 = b0 ? ud : d0; i0 = b0 ? ui : i0;
    };

    const int scan_hi = min(sege, fill_hi);
    const int base = segs + q;
    const int n_it = (scan_hi > base) ? ((scan_hi - base + TPP - 1) / TPP) : 0;
    const int n_b4 = n_it & ~3;

    int i = 0;
    for (; i < n_b4; i += 4) {
        const int j0 = base + i * TPP - seg_lo;
        float4 c0 = pos4[j0];
        float4 c1 = pos4[j0 + TPP];
        float4 c2 = pos4[j0 + 2 * TPP];
        float4 c3 = pos4[j0 + 3 * TPP];
        float s0 = fmaf(nx, c0.x, fmaf(ny, c0.y, fmaf(nz, c0.z, c0.w)));
        float s1 = fmaf(nx, c1.x, fmaf(ny, c1.y, fmaf(nz, c1.z, c1.w)));
        float s2 = fmaf(nx, c2.x, fmaf(ny, c2.y, fmaf(nz, c2.z, c2.w)));
        float s3 = fmaf(nx, c3.x, fmaf(ny, c3.y, fmaf(nz, c3.z, c3.w)));
        float mn = fminf(fminf(s0, s1), fminf(s2, s3));
        if (mn < d2) {              // rare
            if (s0 < d2) ins(s0, base + i * TPP);
            if (s1 < d2) ins(s1, base + (i + 1) * TPP);
            if (s2 < d2) ins(s2, base + (i + 2) * TPP);
            if (s3 < d2) ins(s3, base + (i + 3) * TPP);
        }
    }
    for (; i < n_it; ++i) {
        const int j = base + i * TPP;
        float4 c = pos4[j - seg_lo];
        float s = fmaf(nx, c.x, fmaf(ny, c.y, fmaf(nz, c.z, c.w)));
        if (s < d2) ins(s, j);
    }
    // overflow safety (boundary blocks only): continue from global
    for (int j = base + n_it * TPP; j < sege; j += TPP) {
        float cx = pos[3 * j + 0], cy = pos[3 * j + 1], cz = pos[3 * j + 2];
        float cw = fmaf(cx, cx, fmaf(cy, cy, cz * cz));
        float s = fmaf(nx, cx, fmaf(ny, cy, fmaf(nz, cz, cw)));
        if (s < d2) ins(s, j);
    }

    // ---- merge across the 8 lanes of this point ----
    #pragma unroll
    for (int m = 1; m <= 4; m <<= 1) {
        float e0 = __shfl_xor_sync(0xFFFFFFFFu, d0, m);
        float e1 = __shfl_xor_sync(0xFFFFFFFFu, d1, m);
        float e2 = __shfl_xor_sync(0xFFFFFFFFu, d2, m);
        int   f0 = __shfl_xor_sync(0xFFFFFFFFu, i0, m);
        int   f1 = __shfl_xor_sync(0xFFFFFFFFu, i1, m);
        int   f2 = __shfl_xor_sync(0xFFFFFFFFu, i2, m);
        ins(e0, f0); ins(e1, f1); ins(e2, f2);
    }

    if (q == 0) {
        // exact squared distances for the 3 winners (smem when resident)
        auto fetch = [&](int idx) -> float3 {
            if (idx >= seg_lo && idx < fill_hi) {
                float4 c = pos4[idx - seg_lo];
                return make_float3(c.x, c.y, c.z);
            }
            return make_float3(pos[3 * idx + 0], pos[3 * idx + 1], pos[3 * idx + 2]);
        };
        float3 c0 = fetch(i0), c1 = fetch(i1), c2 = fetch(i2);
        float ax = c0.x - px, ay = c0.y - py, az = c0.z - pz;
        float bx = c1.x - px, by = c1.y - py, bz = c1.z - pz;
        float cx = c2.x - px, cy = c2.y - py, cz = c2.z - pz;
        float e0 = fmaf(ax, ax, fmaf(ay, ay, az * az));
        float e1 = fmaf(bx, bx, fmaf(by, by, bz * bz));
        float e2 = fmaf(cx, cx, fmaf(cy, cy, cz * cz));
        float w0 = 1.0f / fmaxf(e0, 1e-16f);
        float w1v = 1.0f / fmaxf(e1, 1e-16f);
        float w2v = 1.0f / fmaxf(e2, 1e-16f);
        float inv_sw = 1.0f / (w0 + w1v + w2v);
        sIdx[p_local][0] = i0; sIdx[p_local][1] = i1; sIdx[p_local][2] = i2;
        sW[p_local][0] = w0 * inv_sw; sW[p_local][1] = w1v * inv_sw; sW[p_local][2] = w2v * inv_sw;

        if (out_size > NS * HID) {
            out[NS * HID + 3 * gp + 0] = px;
            out[NS * HID + 3 * gp + 1] = py;
            out[NS * HID + 3 * gp + 2] = pz;
            out[NS * HID + NS * 3 + gp] = (float)mb;
        }
    }
    __syncthreads();

    // ---- phase 2: warp-cooperative gather + packed bf16 split store ----
    const int warp = tid >> 5;
    const int lane = tid & 31;

    for (int r = warp; r < PPB; r += 8) {
        const int g  = blockIdx.x * PPB + r;
        const int j0 = sIdx[r][0], j1 = sIdx[r][1], j2 = sIdx[r][2];
        const float a = sW[r][0], b = sW[r][1], c = sW[r][2];

        const float4* X0 = (const float4*)(x + (size_t)j0 * CCH);
        const float4* X1 = (const float4*)(x + (size_t)j1 * CCH);
        const float4* X2 = (const float4*)(x + (size_t)j2 * CCH);
        unsigned short* Y = g_ycat + (size_t)g * (2 * DIN);

        #pragma unroll
        for (int v = lane; v < CCH / 4; v += 32) {
            float4 A = X0[v], B = X1[v], Cv = X2[v];
            float4 o;
            o.x = fmaf(a, A.x, fmaf(b, B.x, c * Cv.x));
            o.y = fmaf(a, A.y, fmaf(b, B.y, c * Cv.y));
            o.z = fmaf(a, A.z, fmaf(b, B.z, c * Cv.z));
            o.w = fmaf(a, A.w, fmaf(b, B.w, c * Cv.w));
            split_store4(Y + v * 4, Y + DIN + v * 4, o);
        }
        float4 sv = ((const float4*)(x_skip + (size_t)g * CS))[lane];
        split_store4(Y + CCH + lane * 4, Y + DIN + CCH + lane * 4, sv);
    }
}

// ---------------------------------------------------------------------------
// bf16x3 mma.sync GEMM: C[M,256] = relu(A @ B^T + bias)
// CTA tile 128x128, BK=32, 256 threads (8 warps = 4m x 2n), 3-stage cp.async.
// ---------------------------------------------------------------------------
#define GSTAGES 3
#define GEMM_SMEM (GSTAGES * 32768)

template<int K, bool PACK>
__global__ __launch_bounds__(256, 1)
void mma_gemm(const unsigned short* __restrict__ Apk,
              const unsigned short* __restrict__ Bpk,
              const float* __restrict__ bias,
              void* __restrict__ Cout)
{
    constexpr int NCHK = K / 32;
    extern __shared__ uint8_t smem[];
    const uint32_t sb = smem_u32(smem);

    const int tid   = threadIdx.x;
    const int lane  = tid & 31;
    const int wid   = tid >> 5;
    const int warpM = wid & 3;
    const int warpN = wid >> 2;
    const int m0    = blockIdx.x * 128;
    const int n0    = blockIdx.y * 128;

    const uint8_t* Abytes = (const uint8_t*)Apk + (size_t)m0 * (4 * K);
    const uint8_t* Bbytes = (const uint8_t*)Bpk + (size_t)n0 * (4 * K);

    auto issue = [&](int kc, int st) {
        uint32_t sA = sb + st * 32768, sB = sA + 16384;
        #pragma unroll
        for (int i = 0; i < 4; ++i) {
            int id  = tid + 256 * i;
            int row = id >> 3, g = id & 7;
            int off = row * (4 * K) + (g < 4 ? kc * 64 + g * 16
                                             : 2 * K + kc * 64 + (g - 4) * 16);
            uint32_t d = (uint32_t)(row * 128) + (uint32_t)((g ^ (row & 7)) << 4);
            cp16(sA + d, Abytes + off);
            cp16(sB + d, Bbytes + off);
        }
        cp_commit();
    };

    issue(0, 0);
    issue(1, 1);

    float acc[2][8][4] = {};

    for (int c = 0; c < NCHK; ++c) {
        if (c <= NCHK - 2) cp_wait<1>(); else cp_wait<0>();
        __syncthreads();

        const int st = c % GSTAGES;
        const uint32_t sA = sb + st * 32768, sB = sA + 16384;

        #pragma unroll
        for (int kk = 0; kk < 2; ++kk) {
            uint32_t ah[2][4], al[2][4];
            #pragma unroll
            for (int mf = 0; mf < 2; ++mf) {
                const int rm  = warpM * 32 + mf * 16 + (lane & 15);
                const int sub = lane >> 4;
                const uint32_t base = sA + rm * 128;
                ldm4(ah[mf], base + (((kk * 2 + sub) ^ (rm & 7)) << 4));
                ldm4(al[mf], base + (((4 + kk * 2 + sub) ^ (rm & 7)) << 4));
            }
            uint32_t bh[8][2], bl[8][2];
            #pragma unroll
            for (int nq = 0; nq < 4; ++nq) {
                const int rn  = warpN * 64 + nq * 16 + (lane & 7) + ((lane >> 4) << 3);
                const int sub = (lane >> 3) & 1;
                const uint32_t base = sB + rn * 128;
                uint32_t t[4];
                ldm4(t, base + (((kk * 2 + sub) ^ (rn & 7)) << 4));
                bh[2 * nq][0] = t[0]; bh[2 * nq][1] = t[1];
                bh[2 * nq + 1][0] = t[2]; bh[2 * nq + 1][1] = t[3];
                ldm4(t, base + (((4 + kk * 2 + sub) ^ (rn & 7)) << 4));
                bl[2 * nq][0] = t[0]; bl[2 * nq][1] = t[1];
                bl[2 * nq + 1][0] = t[2]; bl[2 * nq + 1][1] = t[3];
            }
            #pragma unroll
            for (int mf = 0; mf < 2; ++mf)
                #pragma unroll
                for (int nf = 0; nf < 8; ++nf) {
                    mma16816(acc[mf][nf], ah[mf], bh[nf]);
                    mma16816(acc[mf][nf], ah[mf], bl[nf]);
                    mma16816(acc[mf][nf], al[mf], bh[nf]);
                }
        }

        if (c + GSTAGES - 1 < NCHK) issue(c + GSTAGES - 1, (c + GSTAGES - 1) % GSTAGES);
    }

    #pragma unroll
    for (int mf = 0; mf < 2; ++mf) {
        const int mrow = m0 + warpM * 32 + mf * 16 + (lane >> 2);
        #pragma unroll
        for (int nf = 0; nf < 8; ++nf) {
            const int n = n0 + warpN * 64 + nf * 8 + 2 * (lane & 3);
            const float b0v = __ldg(bias + n), b1v = __ldg(bias + n + 1);
            float v00 = fmaxf(acc[mf][nf][0] + b0v, 0.0f);
            float v01 = fmaxf(acc[mf][nf][1] + b1v, 0.0f);
            float v10 = fmaxf(acc[mf][nf][2] + b0v, 0.0f);
            float v11 = fmaxf(acc[mf][nf][3] + b1v, 0.0f);
            if (PACK) {
                unsigned short* H = (unsigned short*)Cout;
                uint32_t hi0 = pack_bf2(v00, v01);
                float g0 = __uint_as_float(hi0 << 16), g1 = __uint_as_float(hi0 & 0xFFFF0000u);
                uint32_t lo0 = pack_bf2(v00 - g0, v01 - g1);
                uint32_t hi1 = pack_bf2(v10, v11);
                float g2 = __uint_as_float(hi1 << 16), g3 = __uint_as_float(hi1 & 0xFFFF0000u);
                uint32_t lo1 = pack_bf2(v10 - g2, v11 - g3);
                *(uint32_t*)(H + (size_t)mrow * (2 * HID) + n)             = hi0;
                *(uint32_t*)(H + (size_t)mrow * (2 * HID) + HID + n)       = lo0;
                *(uint32_t*)(H + (size_t)(mrow + 8) * (2 * HID) + n)       = hi1;
                *(uint32_t*)(H + (size_t)(mrow + 8) * (2 * HID) + HID + n) = lo1;
            } else {
                float* O = (float*)Cout;
                float2 p0 = {v00, v01}, p1 = {v10, v11};
                *(float2*)(O + (size_t)mrow * 256 + n)       = p0;
                *(float2*)(O + (size_t)(mrow + 8) * 256 + n) = p1;
            }
        }
    }
}

// ---------------------------------------------------------------------------
extern "C" void kernel_launch(void* const* d_in, const int* in_sizes, int n_in,
                              void* d_out, int out_size)
{
    const float* x          = (const float*)d_in[0];
    const float* pos        = (const float*)d_in[1];
    const int*   batch      = (const int*)  d_in[2];
    const float* x_skip     = (const float*)d_in[3];
    const float* pos_skip   = (const float*)d_in[4];
    const int*   batch_skip = (const int*)  d_in[5];
    const float* W1         = (const float*)d_in[6];
    const float* b1         = (const float*)d_in[7];
    const float* W2         = (const float*)d_in[8];
    const float* b2         = (const float*)d_in[9];
    float* out = (float*)d_out;

    unsigned short *ycat, *h, *w1, *w2;
    cudaGetSymbolAddress((void**)&ycat, g_ycat);
    cudaGetSymbolAddress((void**)&h,    g_h);
    cudaGetSymbolAddress((void**)&w1,   g_w1);
    cudaGetSymbolAddress((void**)&w2,   g_w2);

    cudaFuncSetAttribute(knn_interp_kernel,    cudaFuncAttributeMaxDynamicSharedMemorySize, KNN_SMEM);
    cudaFuncSetAttribute(mma_gemm<DIN, true>,  cudaFuncAttributeMaxDynamicSharedMemorySize, GEMM_SMEM);
    cudaFuncSetAttribute(mma_gemm<HID, false>, cudaFuncAttributeMaxDynamicSharedMemorySize, GEMM_SMEM);

    // 1) KNN + interpolate + concat (+ weight prep + tail outputs)
    knn_interp_kernel<<<NS / PPB, 256, KNN_SMEM>>>(x, pos, batch, x_skip, pos_skip, batch_skip,
                                                   W1, W2, out, out_size);

    // 2) h = relu(ycat @ W1 + b1)  — packed bf16 output
    {
        dim3 grid(NS / 128, 2);
        mma_gemm<DIN, true><<<grid, 256, GEMM_SMEM>>>(ycat, w1, b1, h);
    }
    // 3) out = relu(h @ W2 + b2)   — fp32 output
    {
        dim3 grid(NS / 128, 2);
        mma_gemm<HID, false><<<grid, 256, GEMM_SMEM>>>(h, w2, b2, out);
    }
}

// round 15
// speedup vs baseline: 1.4769x; 1.0247x over previous
#include <cuda_runtime.h>
#include <cuda_bf16.h>
#include <cstdint>

#define NC   4096
#define NS   16384
#define CCH  256
#define CS   128
#define DIN  384
#define HID  256

// Packed split-bf16 buffers: row = [hi(K) | lo(K)] bf16.
__device__ __align__(16) unsigned short g_xp [(size_t)NC * (2 * CCH)];   // x packed      [4096][512]
__device__ __align__(16) unsigned short g_xsp[(size_t)NS * (2 * CS)];    // x_skip packed [16384][256]
__device__ __align__(16) unsigned short g_h  [(size_t)NS * (2 * HID)];   // hidden packed [16384][512]
__device__ __align__(16) unsigned short g_w1a[HID * (2 * CCH)];          // W1a^T packed  [256][512]
__device__ __align__(16) unsigned short g_w1b[HID * (2 * CS)];           // W1b^T packed  [256][256]
__device__ __align__(16) unsigned short g_w2 [HID * (2 * HID)];          // W2^T packed   [256][512]
__device__ __align__(16) float g_P[(size_t)NC * HID];                    // P = x @ W1a   [4096][256]
__device__ __align__(16) float g_z[(size_t)NS * HID];                    // z = interp(P) [16384][256]

// ---------------------------------------------------------------------------
// helpers
// ---------------------------------------------------------------------------
__device__ __forceinline__ uint32_t smem_u32(const void* p) {
    uint32_t a;
    asm("{ .reg .u64 t; cvta.to.shared.u64 t, %1; cvt.u32.u64 %0, t; }" : "=r"(a) : "l"(p));
    return a;
}
__device__ __forceinline__ void cp16(uint32_t dst, const void* src) {
    asm volatile("cp.async.cg.shared.global [%0], [%1], 16;" :: "r"(dst), "l"(src));
}
__device__ __forceinline__ void cp_commit() { asm volatile("cp.async.commit_group;"); }
template<int N> __device__ __forceinline__ void cp_wait() {
    asm volatile("cp.async.wait_group %0;" :: "n"(N));
}
__device__ __forceinline__ void ldm4(uint32_t* r, uint32_t a) {
    asm volatile("ldmatrix.sync.aligned.m8n8.x4.shared.b16 {%0,%1,%2,%3}, [%4];"
                 : "=r"(r[0]), "=r"(r[1]), "=r"(r[2]), "=r"(r[3]) : "r"(a));
}
__device__ __forceinline__ void mma16816(float* c, const uint32_t* a, const uint32_t* b) {
    asm volatile("mma.sync.aligned.m16n8k16.row.col.f32.bf16.bf16.f32 "
                 "{%0,%1,%2,%3},{%4,%5,%6,%7},{%8,%9},{%0,%1,%2,%3};"
                 : "+f"(c[0]), "+f"(c[1]), "+f"(c[2]), "+f"(c[3])
                 : "r"(a[0]), "r"(a[1]), "r"(a[2]), "r"(a[3]), "r"(b[0]), "r"(b[1]));
}
__device__ __forceinline__ unsigned short f2bf(float v) {
    return __bfloat16_as_ushort(__float2bfloat16_rn(v));
}
__device__ __forceinline__ float bf2f(unsigned short u) {
    return __bfloat162float(__ushort_as_bfloat16(u));
}
__device__ __forceinline__ uint32_t pack_bf2(float a, float b) {
    __nv_bfloat162 h = __float22bfloat162_rn(make_float2(a, b));
    return *(uint32_t*)&h;
}
__device__ __forceinline__ void split_store4(unsigned short* hi, unsigned short* lo, float4 o) {
    uint32_t ha = pack_bf2(o.x, o.y);
    uint32_t hb = pack_bf2(o.z, o.w);
    float f0 = __uint_as_float(ha << 16), f1 = __uint_as_float(ha & 0xFFFF0000u);
    float f2 = __uint_as_float(hb << 16), f3 = __uint_as_float(hb & 0xFFFF0000u);
    uint32_t la = pack_bf2(o.x - f0, o.y - f1);
    uint32_t lb = pack_bf2(o.z - f2, o.w - f3);
    *(uint2*)hi = make_uint2(ha, hb);
    *(uint2*)lo = make_uint2(la, lb);
}

// ---------------------------------------------------------------------------
// Kernel 0: prep — pack x and W1a^T (inputs to the P gemm)
// ---------------------------------------------------------------------------
__global__ __launch_bounds__(256)
void prep_kernel(const float* __restrict__ x, const float* __restrict__ W1)
{
    const int gid = blockIdx.x * 256 + threadIdx.x;   // 32768 threads
    // pack x: 4096 rows x 64 float4 chunks
    for (int i = gid; i < NC * (CCH / 4); i += 128 * 256) {
        int r = i >> 6, c4 = i & 63;
        float4 v = *(const float4*)(x + (size_t)r * CCH + c4 * 4);
        unsigned short* Y = g_xp + (size_t)r * (2 * CCH);
        split_store4(Y + c4 * 4, Y + CCH + c4 * 4, v);
    }
    // pack W1a^T: W1 rows k = 0..255 (the y part)
    for (int i = gid; i < CCH * HID; i += 128 * 256) {
        int k = i >> 8, n = i & 255;
        float v = W1[i];                     // W1[k][n], k<256
        unsigned short hh = f2bf(v);
        g_w1a[(size_t)n * (2 * CCH) + k]        = hh;
        g_w1a[(size_t)n * (2 * CCH) + CCH + k]  = f2bf(v - bf2f(hh));
    }
}

// ---------------------------------------------------------------------------
// Kernel 2: KNN — PPB=32/TPP=8, segment-resident smem, dot-form rank scan.
// Phase 2 gathers P rows (fp32) into z. Also packs x_skip, W1b^T, W2^T.
// ---------------------------------------------------------------------------
#define SEG_CAP  1664                 // float4 slots (26KB)
#define KNN_SMEM (SEG_CAP * 16)
#define NBATCH   4
#define PPB      32
#define TPP      8

__global__ __launch_bounds__(256, 8)
void knn_interp_kernel(const float* __restrict__ pos,
                       const int*   __restrict__ batch,
                       const float* __restrict__ x_skip,
                       const float* __restrict__ pos_skip,
                       const int*   __restrict__ batch_skip,
                       const float* __restrict__ W1,
                       const float* __restrict__ W2,
                       const float* __restrict__ P,
                       float* __restrict__ out, int out_size)
{
    extern __shared__ float4 pos4[];
    __shared__ int   sIdx[PPB][3];
    __shared__ float sW[PPB][3];
    __shared__ int   sSegB[NBATCH + 1];

    const int tid = threadIdx.x;
    const int p_local = tid >> 3;
    const int q       = tid & 7;
    const int gp      = blockIdx.x * PPB + p_local;
    const int gid     = blockIdx.x * 256 + tid;

    // ---- batch boundary table ----
    if (tid <= NBATCH) {
        int b = tid;
        int v;
        if (b == 0) v = 0;
        else if (b == NBATCH) v = NC;
        else {
            int lo = 0, hi = NC;
            while (lo < hi) { int m = (lo + hi) >> 1; if (batch[m] < b) lo = m + 1; else hi = m; }
            v = lo;
        }
        sSegB[b] = v;
    }

    // ---- pack x_skip [16384][hi 128|lo 128] (float4 chunks) ----
    for (int i = gid; i < NS * (CS / 4); i += 512 * 256) {
        int r = i >> 5, c4 = i & 31;
        float4 v = *(const float4*)(x_skip + (size_t)r * CS + c4 * 4);
        unsigned short* Y = g_xsp + (size_t)r * (2 * CS);
        split_store4(Y + c4 * 4, Y + CS + c4 * 4, v);
    }
    // ---- pack W1b^T: W1 rows k = 256..383 ----
    for (int i = gid; i < CS * HID; i += 512 * 256) {
        int k = i >> 8, n = i & 255;
        float v = W1[(size_t)(CCH + k) * HID + n];
        unsigned short hh = f2bf(v);
        g_w1b[(size_t)n * (2 * CS) + k]       = hh;
        g_w1b[(size_t)n * (2 * CS) + CS + k]  = f2bf(v - bf2f(hh));
    }
    // ---- pack W2^T ----
    for (int i = gid; i < HID * HID; i += 512 * 256) {
        int k = i >> 8, n = i & 255;
        float v = W2[i];
        unsigned short hh = f2bf(v);
        g_w2[(size_t)n * (2 * HID) + k]       = hh;
        g_w2[(size_t)n * (2 * HID) + HID + k] = f2bf(v - bf2f(hh));
    }

    __syncthreads();

    // ---- block segment union + own bounds ----
    const int mbLo = batch_skip[blockIdx.x * PPB];
    const int mbHi = batch_skip[blockIdx.x * PPB + PPB - 1];
    const int seg_lo  = sSegB[mbLo];
    const int fill_hi = min(sSegB[mbHi + 1], seg_lo + SEG_CAP);

    const float px = pos_skip[3 * gp + 0];
    const float py = pos_skip[3 * gp + 1];
    const float pz = pos_skip[3 * gp + 2];
    const int   mb = batch_skip[gp];
    const int   segs = sSegB[mb];
    const int   sege = sSegB[mb + 1];

    // ---- fill smem with union segment ----
    for (int j = seg_lo + tid; j < fill_hi; j += 256) {
        float cx = pos[3 * j + 0], cy = pos[3 * j + 1], cz = pos[3 * j + 2];
        pos4[j - seg_lo] = make_float4(cx, cy, cz, fmaf(cx, cx, fmaf(cy, cy, cz * cz)));
    }
    __syncthreads();

    // ---- phase 1: 1/8-segment scan on d' = |c|^2 - 2 p.c ----
    const float nx = -2.0f * px, ny = -2.0f * py, nz = -2.0f * pz;
    float d0 = 3e38f, d1 = 3e38f, d2 = 3e38f;
    int   i0 = segs,  i1 = segs,  i2 = segs;

    auto ins = [&](float dn, int jn) {
        bool b2 = dn < d2;
        float td = b2 ? dn : d2; int ti = b2 ? jn : i2;
        bool b1 = td < d1;
        d2 = b1 ? d1 : td; i2 = b1 ? i1 : ti;
        float ud = b1 ? td : d1; int ui = b1 ? ti : i1;
        bool b0 = ud < d0;
        d1 = b0 ? d0 : ud; i1 = b0 ? i0 : ui;
        d0 = b0 ? ud : d0; i0 = b0 ? ui : i0;
    };

    const int scan_hi = min(sege, fill_hi);
    int j = segs + q;
    #pragma unroll 4
    for (; j < scan_hi; j += TPP) {
        float4 c = pos4[j - seg_lo];
        float s = fmaf(nx, c.x, fmaf(ny, c.y, fmaf(nz, c.z, c.w)));
        if (s < d2) ins(s, j);      // rare
    }
    for (; j < sege; j += TPP) {    // overflow safety (boundary blocks only)
        float cx = pos[3 * j + 0], cy = pos[3 * j + 1], cz = pos[3 * j + 2];
        float cw = fmaf(cx, cx, fmaf(cy, cy, cz * cz));
        float s = fmaf(nx, cx, fmaf(ny, cy, fmaf(nz, cz, cw)));
        if (s < d2) ins(s, j);
    }

    // ---- merge across the 8 lanes of this point ----
    #pragma unroll
    for (int m = 1; m <= 4; m <<= 1) {
        float e0 = __shfl_xor_sync(0xFFFFFFFFu, d0, m);
        float e1 = __shfl_xor_sync(0xFFFFFFFFu, d1, m);
        float e2 = __shfl_xor_sync(0xFFFFFFFFu, d2, m);
        int   f0 = __shfl_xor_sync(0xFFFFFFFFu, i0, m);
        int   f1 = __shfl_xor_sync(0xFFFFFFFFu, i1, m);
        int   f2 = __shfl_xor_sync(0xFFFFFFFFu, i2, m);
        ins(e0, f0); ins(e1, f1); ins(e2, f2);
    }

    if (q == 0) {
        auto fetch = [&](int idx) -> float3 {
            if (idx >= seg_lo && idx < fill_hi) {
                float4 c = pos4[idx - seg_lo];
                return make_float3(c.x, c.y, c.z);
            }
            return make_float3(pos[3 * idx + 0], pos[3 * idx + 1], pos[3 * idx + 2]);
        };
        float3 c0 = fetch(i0), c1 = fetch(i1), c2 = fetch(i2);
        float ax = c0.x - px, ay = c0.y - py, az = c0.z - pz;
        float bx = c1.x - px, by = c1.y - py, bz = c1.z - pz;
        float cx = c2.x - px, cy = c2.y - py, cz = c2.z - pz;
        float e0 = fmaf(ax, ax, fmaf(ay, ay, az * az));
        float e1 = fmaf(bx, bx, fmaf(by, by, bz * bz));
        float e2 = fmaf(cx, cx, fmaf(cy, cy, cz * cz));
        float w0 = 1.0f / fmaxf(e0, 1e-16f);
        float w1v = 1.0f / fmaxf(e1, 1e-16f);
        float w2v = 1.0f / fmaxf(e2, 1e-16f);
        float inv_sw = 1.0f / (w0 + w1v + w2v);
        sIdx[p_local][0] = i0; sIdx[p_local][1] = i1; sIdx[p_local][2] = i2;
        sW[p_local][0] = w0 * inv_sw; sW[p_local][1] = w1v * inv_sw; sW[p_local][2] = w2v * inv_sw;

        if (out_size > NS * HID) {
            out[NS * HID + 3 * gp + 0] = px;
            out[NS * HID + 3 * gp + 1] = py;
            out[NS * HID + 3 * gp + 2] = pz;
            out[NS * HID + NS * 3 + gp] = (float)mb;
        }
    }
    __syncthreads();

    // ---- phase 2: gather P rows (fp32) -> z ----
    const int warp = tid >> 5;
    const int lane = tid & 31;

    for (int r = warp; r < PPB; r += 8) {
        const int g  = blockIdx.x * PPB + r;
        const int j0 = sIdx[r][0], j1 = sIdx[r][1], j2 = sIdx[r][2];
        const float a = sW[r][0], b = sW[r][1], c = sW[r][2];

        const float4* P0 = (const float4*)(P + (size_t)j0 * HID);
        const float4* P1 = (const float4*)(P + (size_t)j1 * HID);
        const float4* P2 = (const float4*)(P + (size_t)j2 * HID);
        float4* Z = (float4*)(g_z + (size_t)g * HID);

        #pragma unroll
        for (int v = lane; v < HID / 4; v += 32) {
            float4 A = P0[v], B = P1[v], Cv = P2[v];
            float4 o;
            o.x = fmaf(a, A.x, fmaf(b, B.x, c * Cv.x));
            o.y = fmaf(a, A.y, fmaf(b, B.y, c * Cv.y));
            o.z = fmaf(a, A.z, fmaf(b, B.z, c * Cv.z));
            o.w = fmaf(a, A.w, fmaf(b, B.w, c * Cv.w));
            Z[v] = o;
        }
    }
}

// ---------------------------------------------------------------------------
// bf16x3 mma.sync GEMM: C[M,256] = epilogue(A @ B^T)
// MODE 0: C = acc (fp32, no bias/relu)            [P gemm]
// MODE 1: C = pack(relu(acc + z + bias))          [gemm1b -> g_h]
// MODE 2: C = relu(acc + bias) (fp32)             [gemm2 -> out]
// CTA tile 128x128, BK=32, 256 threads, 3-stage cp.async.
// ---------------------------------------------------------------------------
#define GSTAGES 3
#define GEMM_SMEM (GSTAGES * 32768)

template<int K, int MODE>
__global__ __launch_bounds__(256, 1)
void mma_gemm(const unsigned short* __restrict__ Apk,
              const unsigned short* __restrict__ Bpk,
              const float* __restrict__ bias,
              const float* __restrict__ zadd,
              void* __restrict__ Cout)
{
    constexpr int NCHK = K / 32;
    extern __shared__ uint8_t smem[];
    const uint32_t sb = smem_u32(smem);

    const int tid   = threadIdx.x;
    const int lane  = tid & 31;
    const int wid   = tid >> 5;
    const int warpM = wid & 3;
    const int warpN = wid >> 2;
    const int m0    = blockIdx.x * 128;
    const int n0    = blockIdx.y * 128;

    const uint8_t* Abytes = (const uint8_t*)Apk + (size_t)m0 * (4 * K);
    const uint8_t* Bbytes = (const uint8_t*)Bpk + (size_t)n0 * (4 * K);

    auto issue = [&](int kc, int st) {
        uint32_t sA = sb + st * 32768, sB = sA + 16384;
        #pragma unroll
        for (int i = 0; i < 4; ++i) {
            int id  = tid + 256 * i;
            int row = id >> 3, g = id & 7;
            int off = row * (4 * K) + (g < 4 ? kc * 64 + g * 16
                                             : 2 * K + kc * 64 + (g - 4) * 16);
            uint32_t d = (uint32_t)(row * 128) + (uint32_t)((g ^ (row & 7)) << 4);
            cp16(sA + d, Abytes + off);
            cp16(sB + d, Bbytes + off);
        }
        cp_commit();
    };

    issue(0, 0);
    issue(1, 1);

    float acc[2][8][4] = {};

    for (int c = 0; c < NCHK; ++c) {
        if (c <= NCHK - 2) cp_wait<1>(); else cp_wait<0>();
        __syncthreads();

        const int st = c % GSTAGES;
        const uint32_t sA = sb + st * 32768, sB = sA + 16384;

        #pragma unroll
        for (int kk = 0; kk < 2; ++kk) {
            uint32_t ah[2][4], al[2][4];
            #pragma unroll
            for (int mf = 0; mf < 2; ++mf) {
                const int rm  = warpM * 32 + mf * 16 + (lane & 15);
                const int sub = lane >> 4;
                const uint32_t base = sA + rm * 128;
                ldm4(ah[mf], base + (((kk * 2 + sub) ^ (rm & 7)) << 4));
                ldm4(al[mf], base + (((4 + kk * 2 + sub) ^ (rm & 7)) << 4));
            }
            uint32_t bh[8][2], bl[8][2];
            #pragma unroll
            for (int nq = 0; nq < 4; ++nq) {
                const int rn  = warpN * 64 + nq * 16 + (lane & 7) + ((lane >> 4) << 3);
                const int sub = (lane >> 3) & 1;
                const uint32_t base = sB + rn * 128;
                uint32_t t[4];
                ldm4(t, base + (((kk * 2 + sub) ^ (rn & 7)) << 4));
                bh[2 * nq][0] = t[0]; bh[2 * nq][1] = t[1];
                bh[2 * nq + 1][0] = t[2]; bh[2 * nq + 1][1] = t[3];
                ldm4(t, base + (((4 + kk * 2 + sub) ^ (rn & 7)) << 4));
                bl[2 * nq][0] = t[0]; bl[2 * nq][1] = t[1];
                bl[2 * nq + 1][0] = t[2]; bl[2 * nq + 1][1] = t[3];
            }
            #pragma unroll
            for (int mf = 0; mf < 2; ++mf)
                #pragma unroll
                for (int nf = 0; nf < 8; ++nf) {
                    mma16816(acc[mf][nf], ah[mf], bh[nf]);
                    mma16816(acc[mf][nf], ah[mf], bl[nf]);
                    mma16816(acc[mf][nf], al[mf], bh[nf]);
                }
        }

        if (c + GSTAGES - 1 < NCHK) issue(c + GSTAGES - 1, (c + GSTAGES - 1) % GSTAGES);
    }

    #pragma unroll
    for (int mf = 0; mf < 2; ++mf) {
        const int mrow = m0 + warpM * 32 + mf * 16 + (lane >> 2);
        #pragma unroll
        for (int nf = 0; nf < 8; ++nf) {
            const int n = n0 + warpN * 64 + nf * 8 + 2 * (lane & 3);
            float v00 = acc[mf][nf][0], v01 = acc[mf][nf][1];
            float v10 = acc[mf][nf][2], v11 = acc[mf][nf][3];
            if (MODE != 0) {
                const float b0v = __ldg(bias + n), b1v = __ldg(bias + n + 1);
                v00 += b0v; v01 += b1v; v10 += b0v; v11 += b1v;
            }
            if (MODE == 1) {
                float2 z0 = *(const float2*)(zadd + (size_t)mrow * 256 + n);
                float2 z1 = *(const float2*)(zadd + (size_t)(mrow + 8) * 256 + n);
                v00 = fmaxf(v00 + z0.x, 0.0f); v01 = fmaxf(v01 + z0.y, 0.0f);
                v10 = fmaxf(v10 + z1.x, 0.0f); v11 = fmaxf(v11 + z1.y, 0.0f);
                unsigned short* H = (unsigned short*)Cout;
                uint32_t hi0 = pack_bf2(v00, v01);
                float g0 = __uint_as_float(hi0 << 16), g1 = __uint_as_float(hi0 & 0xFFFF0000u);
                uint32_t lo0 = pack_bf2(v00 - g0, v01 - g1);
                uint32_t hi1 = pack_bf2(v10, v11);
                float g2 = __uint_as_float(hi1 << 16), g3 = __uint_as_float(hi1 & 0xFFFF0000u);
                uint32_t lo1 = pack_bf2(v10 - g2, v11 - g3);
                *(uint32_t*)(H + (size_t)mrow * (2 * HID) + n)             = hi0;
                *(uint32_t*)(H + (size_t)mrow * (2 * HID) + HID + n)       = lo0;
                *(uint32_t*)(H + (size_t)(mrow + 8) * (2 * HID) + n)       = hi1;
                *(uint32_t*)(H + (size_t)(mrow + 8) * (2 * HID) + HID + n) = lo1;
            } else {
                if (MODE == 2) {
                    v00 = fmaxf(v00, 0.0f); v01 = fmaxf(v01, 0.0f);
                    v10 = fmaxf(v10, 0.0f); v11 = fmaxf(v11, 0.0f);
                }
                float* O = (float*)Cout;
                float2 p0 = {v00, v01}, p1 = {v10, v11};
                *(float2*)(O + (size_t)mrow * 256 + n)       = p0;
                *(float2*)(O + (size_t)(mrow + 8) * 256 + n) = p1;
            }
        }
    }
}

// ---------------------------------------------------------------------------
extern "C" void kernel_launch(void* const* d_in, const int* in_sizes, int n_in,
                              void* d_out, int out_size)
{
    const float* x          = (const float*)d_in[0];
    const float* pos        = (const float*)d_in[1];
    const int*   batch      = (const int*)  d_in[2];
    const float* x_skip     = (const float*)d_in[3];
    const float* pos_skip   = (const float*)d_in[4];
    const int*   batch_skip = (const int*)  d_in[5];
    const float* W1         = (const float*)d_in[6];
    const float* b1         = (const float*)d_in[7];
    const float* W2         = (const float*)d_in[8];
    const float* b2         = (const float*)d_in[9];
    float* out = (float*)d_out;

    unsigned short *xp, *xsp, *h, *w1a, *w1b, *w2;
    float *P, *z;
    cudaGetSymbolAddress((void**)&xp,  g_xp);
    cudaGetSymbolAddress((void**)&xsp, g_xsp);
    cudaGetSymbolAddress((void**)&h,   g_h);
    cudaGetSymbolAddress((void**)&w1a, g_w1a);
    cudaGetSymbolAddress((void**)&w1b, g_w1b);
    cudaGetSymbolAddress((void**)&w2,  g_w2);
    cudaGetSymbolAddress((void**)&P,   g_P);
    cudaGetSymbolAddress((void**)&z,   g_z);

    cudaFuncSetAttribute(knn_interp_kernel, cudaFuncAttributeMaxDynamicSharedMemorySize, KNN_SMEM);
    cudaFuncSetAttribute(mma_gemm<CCH, 0>,  cudaFuncAttributeMaxDynamicSharedMemorySize, GEMM_SMEM);
    cudaFuncSetAttribute(mma_gemm<CS,  1>,  cudaFuncAttributeMaxDynamicSharedMemorySize, GEMM_SMEM);
    cudaFuncSetAttribute(mma_gemm<HID, 2>,  cudaFuncAttributeMaxDynamicSharedMemorySize, GEMM_SMEM);

    // 0) pack x, W1a^T
    prep_kernel<<<128, 256>>>(x, W1);

    // 1) P = x @ W1a^T   [4096 x 256] (no bias/relu)
    {
        dim3 grid(NC / 128, 2);
        mma_gemm<CCH, 0><<<grid, 256, GEMM_SMEM>>>(xp, w1a, nullptr, nullptr, P);
    }

    // 2) KNN: weights + gather P -> z; packs x_skip, W1b^T, W2^T; tail outputs
    knn_interp_kernel<<<NS / PPB, 256, KNN_SMEM>>>(pos, batch, x_skip, pos_skip, batch_skip,
                                                   W1, W2, P, out, out_size);

    // 3) h = relu(x_skip @ W1b^T + z + b1)  — packed bf16 output
    {
        dim3 grid(NS / 128, 2);
        mma_gemm<CS, 1><<<grid, 256, GEMM_SMEM>>>(xsp, w1b, b1, z, h);
    }
    // 4) out = relu(h @ W2^T + b2) — fp32 output
    {
        dim3 grid(NS / 128, 2);
        mma_gemm<HID, 2><<<grid, 256, GEMM_SMEM>>>(h, w2, b2, nullptr, out);
    }
}